// round 16
// baseline (speedup 1.0000x reference)
#include <cuda_runtime.h>
#include <cuda_fp16.h>
#include <cstdint>

#define B_   8
#define HW_  16384
#define PB   (256LL*256LL)

// ---------------- scratch ----------------
__device__ float  g_S [2*B_*256*256];
__device__ __half g_S16[2*B_*256*256];
__device__ __half g_ZTT[B_*256*512];
__device__ float  g_G [B_*768*256];
__device__ __half g_Wzz16[768*512];
__device__ __half g_wzT16[512*512];
__device__ __half g_wma16[768*512];
__device__ float  g_bf[768];
__device__ __half g_h16[(size_t)B_*256*HW_];
__device__ __half g_m16[(size_t)B_*256*HW_];
__device__ __half g_w16[768*256];
__device__ __half g_W516[5*256*256];
__device__ __half g_HpT[B_*256*256];
__device__ __half g_MpT[B_*256*256];
__device__ __half g_QT [B_*256*256];
__device__ __half g_KT [B_*256*256];
__device__ __half g_KmT[B_*256*256];
__device__ __half g_V  [B_*256*256];
__device__ __half g_Vm [B_*256*256];

__device__ __forceinline__ float fast_tanh(float x) {
    float r; asm("tanh.approx.f32 %0, %1;" : "=f"(r) : "f"(x)); return r;
}
__device__ __forceinline__ float fast_sig(float x) {
    return 1.0f / (1.0f + __expf(-x));
}

// ---------------- pooling ----------------
__global__ void pool_kernel(const float* __restrict__ h, const float* __restrict__ m)
{
    int tid = threadIdx.x;
    int hw = tid >> 4, l16 = tid & 15;
    const float* src = blockIdx.y ? m : h;
    __half* d16  = blockIdx.y ? g_m16 : g_h16;
    __half* dstT = blockIdx.y ? g_MpT : g_HpT;
    int gh = blockIdx.x * 16 + hw;
    int s0 = gh * 4;

    float4 v[4];
    #pragma unroll
    for (int j = 0; j < 4; j++)
        v[j] = *(const float4*)(src + (size_t)(s0 + j) * 64 + l16 * 4);

    #pragma unroll
    for (int j = 0; j < 4; j++) {
        __half2 p0 = __floats2half2_rn(v[j].x, v[j].y);
        __half2 p1 = __floats2half2_rn(v[j].z, v[j].w);
        uint2 u;
        u.x = *(const uint32_t*)&p0;
        u.y = *(const uint32_t*)&p1;
        *(uint2*)(d16 + (size_t)(s0 + j) * 64 + l16 * 4) = u;
    }

    #pragma unroll
    for (int j = 0; j < 4; j++) {
        float s = v[j].x + v[j].y + v[j].z + v[j].w;
        #pragma unroll
        for (int o = 8; o; o >>= 1) s += __shfl_xor_sync(0xffffffffu, s, o);
        if (l16 == 0) {
            int idx = s0 + j;
            int off = (idx & 0xFF0000) | ((idx & 255) << 8) | ((idx >> 8) & 255);
            dstT[off] = __float2half(s * (1.0f / 64.0f));
        }
    }
}

// ---------------- merged fp16 weight prep ----------------
#define N1_ (768*256)
#define N2_ (5*65536)
#define N3_ (768*512)
#define N4_ (512*512)
__global__ void prep_all(const float* __restrict__ wm,
                         const float* __restrict__ w0, const float* __restrict__ w1,
                         const float* __restrict__ w2, const float* __restrict__ w3,
                         const float* __restrict__ w4,
                         const float* __restrict__ wz)
{
    int i = blockIdx.x * 1024 + threadIdx.x;
    if (i < N1_) {
        int r = i >> 8, k = i & 255;
        g_w16[i] = __float2half(wm[(size_t)r*768 + 512 + k]);
    } else if (i < N1_ + N2_) {
        int i2 = i - N1_;
        const float* w;
        switch (i2 >> 16) {
            case 0: w = w0; break;
            case 1: w = w1; break;
            case 2: w = w2; break;
            case 3: w = w3; break;
            default: w = w4; break;
        }
        g_W516[i2] = __float2half(w[i2 & 65535]);
    } else if (i < N1_ + N2_ + N3_) {
        int i3 = i - N1_ - N2_;
        int r = i3 >> 9, o = i3 & 511;
        g_wma16[i3] = __float2half(wm[(size_t)r*768 + o]);
    } else if (i < N1_ + N2_ + N3_ + N4_) {
        int i4 = i - N1_ - N2_ - N3_;
        int c = i4 >> 9, o = i4 & 511;
        g_wzT16[c*512 + o] = __float2half(wz[(size_t)o*512 + c]);
    }
}

// ------- unified batched fp16 mma GEMM: double-buffered, per-z geometry ---
#define ZMAX 41
struct HU {
    const __half* A[ZMAX];
    const __half* B[ZMAX];
    void*         C[ZMAX];
    const float*  bias[ZMAX];
    int lda[ZMAX], ldb[ZMAX], ldc[ZMAX], K[ZMAX];
    unsigned char mode[ZMAX], mb[ZMAX], nb[ZMAX];
};

__global__ void __launch_bounds__(256) gemm_hu(HU hu)
{
    int z = blockIdx.z;
    if (blockIdx.y >= hu.mb[z] || blockIdx.x >= hu.nb[z]) return;

    __shared__ uint32_t As[2][64*12];
    __shared__ uint32_t Bs[2][64*12];
    int tid = threadIdx.x;
    const __half* Ab = hu.A[z];
    const __half* Bb = hu.B[z];
    int lda = hu.lda[z], ldb = hu.ldb[z], ldc = hu.ldc[z];
    int nk = hu.K[z] >> 4;
    int m0 = blockIdx.y * 64, n0 = blockIdx.x * 64;
    int lane = tid & 31, wid = tid >> 5;
    int wmi = wid >> 2, wni = wid & 3;
    int g = lane >> 2, tg = lane & 3;
    float acc[2][2][4] = {};
    int srow = tid >> 2, sq = tid & 3;

    uint2 av = *(const uint2*)(Ab + (size_t)(m0+srow)*lda + sq*4);
    uint2 bv = *(const uint2*)(Bb + (size_t)(n0+srow)*ldb + sq*4);
    *(uint2*)&As[0][srow*12 + sq*2] = av;
    *(uint2*)&Bs[0][srow*12 + sq*2] = bv;
    __syncthreads();

    for (int kt = 0; kt < nk; kt++) {
        uint2 av2, bv2;
        if (kt + 1 < nk) {
            int k0 = (kt + 1) << 4;
            av2 = *(const uint2*)(Ab + (size_t)(m0+srow)*lda + k0 + sq*4);
            bv2 = *(const uint2*)(Bb + (size_t)(n0+srow)*ldb + k0 + sq*4);
        }
        int cur = kt & 1;
        uint32_t bf[2][2];
        #pragma unroll
        for (int nt = 0; nt < 2; nt++) {
            int nr = wni*16 + nt*8 + g;
            bf[nt][0] = Bs[cur][nr*12 + tg];
            bf[nt][1] = Bs[cur][nr*12 + 4 + tg];
        }
        #pragma unroll
        for (int mt = 0; mt < 2; mt++) {
            int rb = wmi*32 + mt*16;
            uint32_t a0 = As[cur][(rb + g    )*12 + tg];
            uint32_t a1 = As[cur][(rb + 8 + g)*12 + tg];
            uint32_t a2 = As[cur][(rb + g    )*12 + 4 + tg];
            uint32_t a3 = As[cur][(rb + 8 + g)*12 + 4 + tg];
            #pragma unroll
            for (int nt = 0; nt < 2; nt++)
                asm volatile(
                    "mma.sync.aligned.m16n8k16.row.col.f32.f16.f16.f32 "
                    "{%0,%1,%2,%3},{%4,%5,%6,%7},{%8,%9},{%0,%1,%2,%3};\n"
                    : "+f"(acc[mt][nt][0]), "+f"(acc[mt][nt][1]),
                      "+f"(acc[mt][nt][2]), "+f"(acc[mt][nt][3])
                    : "r"(a0), "r"(a1), "r"(a2), "r"(a3),
                      "r"(bf[nt][0]), "r"(bf[nt][1]));
        }
        if (kt + 1 < nk) {
            int nxt = (kt + 1) & 1;
            *(uint2*)&As[nxt][srow*12 + sq*2] = av2;
            *(uint2*)&Bs[nxt][srow*12 + sq*2] = bv2;
            __syncthreads();
        }
    }

    int mode = hu.mode[z];
    const float* bias = hu.bias[z];
    #pragma unroll
    for (int mt = 0; mt < 2; mt++) {
        int r0 = m0 + wmi*32 + mt*16 + g;
        int r1 = r0 + 8;
        float bv0 = bias ? bias[r0] : 0.0f;
        float bv1 = bias ? bias[r1] : 0.0f;
        #pragma unroll
        for (int nt = 0; nt < 2; nt++) {
            int cc = n0 + wni*16 + nt*8 + tg*2;
            float v00 = acc[mt][nt][0] + bv0, v01 = acc[mt][nt][1] + bv0;
            float v10 = acc[mt][nt][2] + bv1, v11 = acc[mt][nt][3] + bv1;
            if (mode == 0) {
                float* C = (float*)hu.C[z];
                *(float2*)&C[(size_t)r0*ldc + cc] = make_float2(v00, v01);
                *(float2*)&C[(size_t)r1*ldc + cc] = make_float2(v10, v11);
            } else if (mode == 1) {
                __half* C = (__half*)hu.C[z];
                *(__half2*)&C[(size_t)r0*ldc + cc] = __floats2half2_rn(v00, v01);
                *(__half2*)&C[(size_t)r1*ldc + cc] = __floats2half2_rn(v10, v11);
            } else {
                __half* C = (__half*)hu.C[z];
                C[(size_t)(cc  )*ldc + r0] = __float2half(v00);
                C[(size_t)(cc+1)*ldc + r0] = __float2half(v01);
                C[(size_t)(cc  )*ldc + r1] = __float2half(v10);
                C[(size_t)(cc+1)*ldc + r1] = __float2half(v11);
            }
        }
    }
}

// ---------------- softmax: warp per row of 256 ----------------
__global__ void softmax_kernel()
{
    int warp = threadIdx.x >> 5, lane = threadIdx.x & 31;
    size_t row = (size_t)blockIdx.x * 8 + warp;
    const float* rp = g_S + row * 256;
    float4 v0 = ((const float4*)rp)[lane*2];
    float4 v1 = ((const float4*)rp)[lane*2 + 1];
    float mx = fmaxf(fmaxf(fmaxf(v0.x, v0.y), fmaxf(v0.z, v0.w)),
                     fmaxf(fmaxf(v1.x, v1.y), fmaxf(v1.z, v1.w)));
    #pragma unroll
    for (int o = 16; o; o >>= 1) mx = fmaxf(mx, __shfl_xor_sync(0xffffffffu, mx, o));
    float e[8];
    e[0] = __expf(v0.x - mx); e[1] = __expf(v0.y - mx);
    e[2] = __expf(v0.z - mx); e[3] = __expf(v0.w - mx);
    e[4] = __expf(v1.x - mx); e[5] = __expf(v1.y - mx);
    e[6] = __expf(v1.z - mx); e[7] = __expf(v1.w - mx);
    float s = e[0]+e[1]+e[2]+e[3]+e[4]+e[5]+e[6]+e[7];
    #pragma unroll
    for (int o = 16; o; o >>= 1) s += __shfl_xor_sync(0xffffffffu, s, o);
    float inv = 1.0f / s;
    __half2 h0 = __floats2half2_rn(e[0]*inv, e[1]*inv);
    __half2 h1 = __floats2half2_rn(e[2]*inv, e[3]*inv);
    __half2 h2 = __floats2half2_rn(e[4]*inv, e[5]*inv);
    __half2 h3 = __floats2half2_rn(e[6]*inv, e[7]*inv);
    uint4 u = { *(uint32_t*)&h0, *(uint32_t*)&h1, *(uint32_t*)&h2, *(uint32_t*)&h3 };
    *(uint4*)(g_S16 + row * 256 + lane * 8) = u;
}

// ---------------- bfold ----------------
__global__ void bfold_kernel(const float* __restrict__ wm,
                             const float* __restrict__ bz,
                             const float* __restrict__ bm)
{
    int r = blockIdx.x, t = threadIdx.x;
    float s = wm[(size_t)r*768 + t] * bz[t]
            + wm[(size_t)r*768 + 256 + t] * bz[256 + t];
    __shared__ float red[8];
    #pragma unroll
    for (int o = 16; o; o >>= 1) s += __shfl_xor_sync(0xffffffffu, s, o);
    if ((t & 31) == 0) red[t >> 5] = s;
    __syncthreads();
    if (t == 0) {
        float tot = bm[r];
        #pragma unroll
        for (int i = 0; i < 8; i++) tot += red[i];
        g_bf[r] = tot;
    }
}

// === fused v4: o-chunk 32, A resident 48KB, single B buffer, 2 blocks/SM ===
// SMEM words: A [0,12288): 96 rows x 128 words, XOR swizzle 4*(q32 ^ (r&7)).
//             B [12288, 28800): 128 px rows x 129 stride. Total 112.5 KB.
// Grid (32, 8, 8): y0=bx*4, m0=by*32, b=bz. 256 threads, warps 2(m) x 4(n).
#define FSM4 115200
#define A_W4 12288

__global__ void __launch_bounds__(256, 2) fused_f16_gate(float* __restrict__ out)
{
    extern __shared__ uint32_t sm[];
    uint32_t* Asm = sm;
    uint32_t* Bsm = sm + A_W4;
    int tid = threadIdx.x, lane = tid & 31, wid = tid >> 5;
    int y0 = blockIdx.x * 4;
    int m0 = blockIdx.y * 32;
    int b  = blockIdx.z;
    int wmi = wid >> 2, wni = wid & 3;
    int g = lane >> 2, tg = lane & 3;

    const __half* Xbase = g_h16 + (size_t)b * 256 * HW_;

    // ---- prologue: stage A (96 rows x 32 uint4, swizzled) ----
    #pragma unroll
    for (int i = 0; i < 12; i++) {
        int slot = tid + 256*i;                 // 0..3071
        int r = slot >> 5, q32 = slot & 31;     // row 0..95
        int grow = (r >> 5) * 256 + m0 + (r & 31);
        uint4 v = *(const uint4*)(g_w16 + (size_t)grow*256 + q32*8);
        *(uint4*)&Asm[r*128 + 4*(q32 ^ (r & 7))] = v;
    }

    int kk = tid >> 4, px8 = tid & 15;          // B staging: kk 0..15, px8 0..15

    // ---- stage B(y0) ----
    {
        const __half* Xy = Xbase + (size_t)y0 * 128;
        uint4 lo[8], hi[8];
        #pragma unroll
        for (int i = 0; i < 8; i++) {
            int kp = i*16 + kk;
            lo[i] = *(const uint4*)(Xy + (size_t)(2*kp  )*HW_ + px8*8);
            hi[i] = *(const uint4*)(Xy + (size_t)(2*kp+1)*HW_ + px8*8);
        }
        #pragma unroll
        for (int i = 0; i < 8; i++) {
            int kp = i*16 + kk;
            const unsigned short* lp = (const unsigned short*)&lo[i];
            const unsigned short* hp = (const unsigned short*)&hi[i];
            #pragma unroll
            for (int j = 0; j < 8; j++)
                Bsm[(px8*8 + j)*129 + kp] = (uint32_t)lp[j] | ((uint32_t)hp[j] << 16);
        }
    }
    __syncthreads();

    const size_t OUT2 = (size_t)B_ * 256 * HW_;

    for (int yi = 0; yi < 4; yi++) {
        int y = y0 + yi;

        // ---- mma: 8 k-chunks, barrier-free ----
        float acc[3][4][4];
        #pragma unroll
        for (int s = 0; s < 3; s++)
            #pragma unroll
            for (int n = 0; n < 4; n++)
                #pragma unroll
                for (int c = 0; c < 4; c++) acc[s][n][c] = 0.0f;

        for (int kc = 0; kc < 8; kc++) {
            #pragma unroll
            for (int ks = 0; ks < 2; ks++) {
                int kp0 = kc*16 + ks*8 + tg;
                uint32_t bfr[4][2];
                #pragma unroll
                for (int nt = 0; nt < 4; nt++) {
                    int n = wni*32 + nt*8 + g;
                    bfr[nt][0] = Bsm[n*129 + kp0];
                    bfr[nt][1] = Bsm[n*129 + kp0 + 4];
                }
                int sw0 = kp0 ^ (g << 2);
                int sw4 = sw0 ^ 4;
                #pragma unroll
                for (int s = 0; s < 3; s++) {
                    int rb = s*32 + wmi*16;
                    uint32_t a0 = Asm[(rb + g    )*128 + sw0];
                    uint32_t a1 = Asm[(rb + 8 + g)*128 + sw0];
                    uint32_t a2 = Asm[(rb + g    )*128 + sw4];
                    uint32_t a3 = Asm[(rb + 8 + g)*128 + sw4];
                    #pragma unroll
                    for (int nt = 0; nt < 4; nt++)
                        asm volatile(
                            "mma.sync.aligned.m16n8k16.row.col.f32.f16.f16.f32 "
                            "{%0,%1,%2,%3},{%4,%5,%6,%7},{%8,%9},{%0,%1,%2,%3};\n"
                            : "+f"(acc[s][nt][0]), "+f"(acc[s][nt][1]),
                              "+f"(acc[s][nt][2]), "+f"(acc[s][nt][3])
                            : "r"(a0), "r"(a1), "r"(a2), "r"(a3),
                              "r"(bfr[nt][0]), "r"(bfr[nt][1]));
                }
            }
        }
        __syncthreads();   // all done reading B(y)

        // ---- stage gy(y) into retired B (96 x 16 floats) ----
        float* gy = (float*)Bsm;
        {
            float sy = (y + 0.5f) * 0.125f - 0.5f; if (sy < 0.0f) sy = 0.0f;
            int yy0 = (int)sy; float fy = sy - (float)yy0; int yy1 = min(yy0 + 1, 15);
            #pragma unroll
            for (int i = 0; i < 6; i++) {
                int idx = tid + 256*i;          // 0..1535
                int r = idx >> 4, px16 = idx & 15;
                int grow = (r >> 5) * 256 + m0 + (r & 31);
                const float* Gb = g_G + ((size_t)b*768 + grow) * 256;
                gy[r*16 + px16] = (1.0f - fy) * Gb[yy0*16 + px16] + fy * Gb[yy1*16 + px16];
            }
        }
        __syncthreads();

        // ---- gating epilogue ----
        #pragma unroll
        for (int rr = 0; rr < 2; rr++) {
            int o_loc  = wmi*16 + rr*8 + g;     // 0..31
            int o_glob = m0 + o_loc;
            float bv0 = g_bf[o_glob];
            float bv1 = g_bf[256 + o_glob];
            float bv2 = g_bf[512 + o_glob];
            const __half* mrow = g_m16 + ((size_t)b*256 + o_glob)*HW_ + (size_t)y*128;
            float* hrow = out + ((size_t)b*256 + o_glob)*HW_ + (size_t)y*128;
            float* mrow_out = hrow + OUT2;
            #pragma unroll
            for (int nt = 0; nt < 4; nt++) {
                int x = wni*32 + nt*8 + tg*2;
                __half2 mh = *(const __half2*)&mrow[x];
                float2 mv = __half22float2(mh);
                float nh[2], nm[2];
                #pragma unroll
                for (int px = 0; px < 2; px++) {
                    int xx = x + px;
                    float sx = (xx + 0.5f) * 0.125f - 0.5f; if (sx < 0.0f) sx = 0.0f;
                    int x0 = (int)sx; float fx = sx - (float)x0; int x1 = min(x0 + 1, 15);
                    float g0 = (1.0f-fx)*gy[(0*32+o_loc)*16 + x0] + fx*gy[(0*32+o_loc)*16 + x1];
                    float g1 = (1.0f-fx)*gy[(1*32+o_loc)*16 + x0] + fx*gy[(1*32+o_loc)*16 + x1];
                    float g2 = (1.0f-fx)*gy[(2*32+o_loc)*16 + x0] + fx*gy[(2*32+o_loc)*16 + x1];
                    int cc = rr*2 + px;
                    float mo = acc[0][nt][cc] + bv0 + g0;
                    float mg = acc[1][nt][cc] + bv1 + g1;
                    float mi = acc[2][nt][cc] + bv2 + g2;
                    float mval = px ? mv.y : mv.x;
                    float gi = fast_sig(mi);
                    float nmv = (1.0f - gi) * mval + gi * fast_tanh(mg);
                    nm[px] = nmv;
                    nh[px] = nmv * fast_sig(mo);
                }
                *(float2*)&hrow[x]     = make_float2(nh[0], nh[1]);
                *(float2*)&mrow_out[x] = make_float2(nm[0], nm[1]);
            }
        }

        // ---- stage B(y+1) (overwrites gy; acc dead) ----
        if (yi < 3) {
            __syncthreads();                    // epilogue gy reads done
            const __half* Xy = Xbase + (size_t)(y+1) * 128;
            uint4 lo[8], hi[8];
            #pragma unroll
            for (int i = 0; i < 8; i++) {
                int kp = i*16 + kk;
                lo[i] = *(const uint4*)(Xy + (size_t)(2*kp  )*HW_ + px8*8);
                hi[i] = *(const uint4*)(Xy + (size_t)(2*kp+1)*HW_ + px8*8);
            }
            #pragma unroll
            for (int i = 0; i < 8; i++) {
                int kp = i*16 + kk;
                const unsigned short* lp = (const unsigned short*)&lo[i];
                const unsigned short* hp = (const unsigned short*)&hi[i];
                #pragma unroll
                for (int j = 0; j < 8; j++)
                    Bsm[(px8*8 + j)*129 + kp] = (uint32_t)lp[j] | ((uint32_t)hp[j] << 16);
            }
            __syncthreads();                    // B(y+1) visible for next mma
        }
    }
}

// ---------------- launcher ----------------
extern "C" void kernel_launch(void* const* d_in, const int* in_sizes, int n_in,
                              void* d_out, int out_size)
{
    const float* h   = (const float*)d_in[0];
    const float* m   = (const float*)d_in[1];
    const float* wq  = (const float*)d_in[2];
    const float* bq  = (const float*)d_in[3];
    const float* wk  = (const float*)d_in[4];
    const float* bk  = (const float*)d_in[5];
    const float* wv  = (const float*)d_in[6];
    const float* bv  = (const float*)d_in[7];
    const float* wkm = (const float*)d_in[8];
    const float* bkm = (const float*)d_in[9];
    const float* wvm = (const float*)d_in[10];
    const float* bvm = (const float*)d_in[11];
    const float* wz  = (const float*)d_in[12];
    const float* bz  = (const float*)d_in[13];
    const float* wm  = (const float*)d_in[14];
    const float* bm  = (const float*)d_in[15];
    float* out = (float*)d_out;

    float *S, *G;
    __half *HpT, *MpT, *W516, *QT, *KT, *KmT, *V, *Vm, *S16, *ZTT, *Wzz16, *wzT16, *wma16;
    cudaGetSymbolAddress((void**)&S,     g_S);
    cudaGetSymbolAddress((void**)&S16,   g_S16);
    cudaGetSymbolAddress((void**)&ZTT,   g_ZTT);
    cudaGetSymbolAddress((void**)&G,     g_G);
    cudaGetSymbolAddress((void**)&Wzz16, g_Wzz16);
    cudaGetSymbolAddress((void**)&wzT16, g_wzT16);
    cudaGetSymbolAddress((void**)&wma16, g_wma16);
    cudaGetSymbolAddress((void**)&HpT,   g_HpT);
    cudaGetSymbolAddress((void**)&MpT,   g_MpT);
    cudaGetSymbolAddress((void**)&W516,  g_W516);
    cudaGetSymbolAddress((void**)&QT,    g_QT);
    cudaGetSymbolAddress((void**)&KT,    g_KT);
    cudaGetSymbolAddress((void**)&KmT,   g_KmT);
    cudaGetSymbolAddress((void**)&V,     g_V);
    cudaGetSymbolAddress((void**)&Vm,    g_Vm);

    cudaFuncSetAttribute(fused_f16_gate,
                         cudaFuncAttributeMaxDynamicSharedMemorySize, FSM4);

    // 1) pooling + prep + bias fold
    pool_kernel<<<dim3(8192, 2), 256>>>(h, m);
    prep_all<<<1152, 1024>>>(wm, wq, wk, wv, wkm, wvm, wz);
    bfold_kernel<<<768, 256>>>(wm, bz, bm);

    // 2) merged: Wzz fold (z=0) + all 5 projections (z=1..40)
    {
        HU hu = {};
        hu.A[0] = wma16; hu.B[0] = wzT16; hu.C[0] = Wzz16; hu.bias[0] = nullptr;
        hu.lda[0] = 512; hu.ldb[0] = 512; hu.ldc[0] = 512; hu.K[0] = 512;
        hu.mode[0] = 1; hu.mb[0] = 12; hu.nb[0] = 8;
        const __half* W5[5] = { W516 + 0*65536, W516 + 1*65536, W516 + 3*65536,
                                W516 + 2*65536, W516 + 4*65536 };
        const float*  b5[5] = { bq, bk, bkm, bv, bvm };
        __half* C5[5] = { QT, KT, KmT, V, Vm };
        const __half* in5[5] = { HpT, HpT, MpT, HpT, MpT };
        for (int s = 0; s < 5; s++)
            for (int bt = 0; bt < 8; bt++) {
                int z = 1 + s*8 + bt;
                hu.A[z] = W5[s];
                hu.B[z] = in5[s] + bt*PB;
                hu.C[z] = C5[s] + bt*PB;
                hu.bias[z] = b5[s];
                hu.lda[z] = 256; hu.ldb[z] = 256; hu.ldc[z] = 256; hu.K[z] = 256;
                hu.mode[z] = (s < 3) ? 2 : 1;
                hu.mb[z] = 4; hu.nb[z] = 4;
            }
        gemm_hu<<<dim3(8, 12, 41), 256>>>(hu);
    }

    // 3) scores (fp32 out)
    {
        HU hu = {};
        for (int z = 0; z < 16; z++) {
            int bt = z & 7;
            hu.A[z] = QT + bt*PB;
            hu.B[z] = ((z < 8) ? KT : KmT) + bt*PB;
            hu.C[z] = S + (long long)z*PB;
            hu.bias[z] = nullptr;
            hu.lda[z] = 256; hu.ldb[z] = 256; hu.ldc[z] = 256; hu.K[z] = 256;
            hu.mode[z] = 0; hu.mb[z] = 4; hu.nb[z] = 4;
        }
        gemm_hu<<<dim3(4, 4, 16), 256>>>(hu);
    }

    // 4) softmax -> S16
    softmax_kernel<<<512, 256>>>();

    // 5) ZTT (transposed fp16 out, ldc=512)
    {
        HU hu = {};
        for (int z = 0; z < 16; z++) {
            int bt = z & 7;
            hu.A[z] = ((z < 8) ? V : Vm) + bt*PB;
            hu.B[z] = S16 + (long long)z*PB;
            hu.C[z] = ZTT + (long long)bt*256*512 + ((z < 8) ? 0 : 256);
            hu.bias[z] = nullptr;
            hu.lda[z] = 256; hu.ldb[z] = 256; hu.ldc[z] = 512; hu.K[z] = 256;
            hu.mode[z] = 2; hu.mb[z] = 4; hu.nb[z] = 4;
        }
        gemm_hu<<<dim3(4, 4, 16), 256>>>(hu);
    }

    // 6) G = Wzz16 . ZTT  (fp32 out, K=512)
    {
        HU hu = {};
        for (int bt = 0; bt < 8; bt++) {
            hu.A[bt] = Wzz16;
            hu.B[bt] = ZTT + (long long)bt*256*512;
            hu.C[bt] = G + (long long)bt*768*256;
            hu.bias[bt] = nullptr;
            hu.lda[bt] = 512; hu.ldb[bt] = 512; hu.ldc[bt] = 256; hu.K[bt] = 512;
            hu.mode[bt] = 0; hu.mb[bt] = 12; hu.nb[bt] = 4;
        }
        gemm_hu<<<dim3(4, 12, 8), 256>>>(hu);
    }

    // 7) fused v4 (2 blocks/SM)
    fused_f16_gate<<<dim3(32, 8, 8), 256, FSM4>>>(out);
}

// round 17
// speedup vs baseline: 1.1842x; 1.1842x over previous
#include <cuda_runtime.h>
#include <cuda_fp16.h>
#include <cstdint>

#define B_   8
#define HW_  16384
#define PB   (256LL*256LL)

// ---------------- scratch ----------------
__device__ __half g_Spre[2*B_*256*256];       // pre-softmax scores fp16
__device__ __half g_S16[2*B_*256*256];        // softmax probs fp16
__device__ __half g_ZTT[B_*256*512];
__device__ float  g_G [B_*768*256];
__device__ __half g_Wzz16[768*512];
__device__ __half g_wzT16[512*512];
__device__ __half g_wma16[768*512];
__device__ float  g_bf[768];
__device__ __half g_h16[(size_t)B_*256*HW_];
__device__ __half g_m16[(size_t)B_*256*HW_];
__device__ __half g_w16[768*256];
__device__ __half g_W516[5*256*256];
__device__ __half g_HpT[B_*256*256];
__device__ __half g_MpT[B_*256*256];
__device__ __half g_QT [B_*256*256];
__device__ __half g_KT [B_*256*256];
__device__ __half g_KmT[B_*256*256];
__device__ __half g_V  [B_*256*256];
__device__ __half g_Vm [B_*256*256];

__device__ __forceinline__ float fast_tanh(float x) {
    float r; asm("tanh.approx.f32 %0, %1;" : "=f"(r) : "f"(x)); return r;
}
__device__ __forceinline__ float fast_sig(float x) {
    return 1.0f / (1.0f + __expf(-x));
}

// ---------------- pooling ----------------
__global__ void pool_kernel(const float* __restrict__ h, const float* __restrict__ m)
{
    int tid = threadIdx.x;
    int hw = tid >> 4, l16 = tid & 15;
    const float* src = blockIdx.y ? m : h;
    __half* d16  = blockIdx.y ? g_m16 : g_h16;
    __half* dstT = blockIdx.y ? g_MpT : g_HpT;
    int gh = blockIdx.x * 16 + hw;
    int s0 = gh * 4;

    float4 v[4];
    #pragma unroll
    for (int j = 0; j < 4; j++)
        v[j] = *(const float4*)(src + (size_t)(s0 + j) * 64 + l16 * 4);

    #pragma unroll
    for (int j = 0; j < 4; j++) {
        __half2 p0 = __floats2half2_rn(v[j].x, v[j].y);
        __half2 p1 = __floats2half2_rn(v[j].z, v[j].w);
        uint2 u;
        u.x = *(const uint32_t*)&p0;
        u.y = *(const uint32_t*)&p1;
        *(uint2*)(d16 + (size_t)(s0 + j) * 64 + l16 * 4) = u;
    }

    #pragma unroll
    for (int j = 0; j < 4; j++) {
        float s = v[j].x + v[j].y + v[j].z + v[j].w;
        #pragma unroll
        for (int o = 8; o; o >>= 1) s += __shfl_xor_sync(0xffffffffu, s, o);
        if (l16 == 0) {
            int idx = s0 + j;
            int off = (idx & 0xFF0000) | ((idx & 255) << 8) | ((idx >> 8) & 255);
            dstT[off] = __float2half(s * (1.0f / 64.0f));
        }
    }
}

// ---------------- merged fp16 weight prep ----------------
#define N1_ (768*256)
#define N2_ (5*65536)
#define N3_ (768*512)
#define N4_ (512*512)
__global__ void prep_all(const float* __restrict__ wm,
                         const float* __restrict__ w0, const float* __restrict__ w1,
                         const float* __restrict__ w2, const float* __restrict__ w3,
                         const float* __restrict__ w4,
                         const float* __restrict__ wz)
{
    int i = blockIdx.x * 1024 + threadIdx.x;
    if (i < N1_) {
        int r = i >> 8, k = i & 255;
        g_w16[i] = __float2half(wm[(size_t)r*768 + 512 + k]);
    } else if (i < N1_ + N2_) {
        int i2 = i - N1_;
        const float* w;
        switch (i2 >> 16) {
            case 0: w = w0; break;
            case 1: w = w1; break;
            case 2: w = w2; break;
            case 3: w = w3; break;
            default: w = w4; break;
        }
        g_W516[i2] = __float2half(w[i2 & 65535]);
    } else if (i < N1_ + N2_ + N3_) {
        int i3 = i - N1_ - N2_;
        int r = i3 >> 9, o = i3 & 511;
        g_wma16[i3] = __float2half(wm[(size_t)r*768 + o]);
    } else if (i < N1_ + N2_ + N3_ + N4_) {
        int i4 = i - N1_ - N2_ - N3_;
        int c = i4 >> 9, o = i4 & 511;
        g_wzT16[c*512 + o] = __float2half(wz[(size_t)o*512 + c]);
    }
}

// ------- unified batched fp16 mma GEMM: double-buffered, per-z geometry ---
#define ZMAX 41
struct HU {
    const __half* A[ZMAX];
    const __half* B[ZMAX];
    void*         C[ZMAX];
    const float*  bias[ZMAX];
    int lda[ZMAX], ldb[ZMAX], ldc[ZMAX], K[ZMAX];
    unsigned char mode[ZMAX], mb[ZMAX], nb[ZMAX];
};

__global__ void __launch_bounds__(256) gemm_hu(HU hu)
{
    int z = blockIdx.z;
    if (blockIdx.y >= hu.mb[z] || blockIdx.x >= hu.nb[z]) return;

    __shared__ uint32_t As[2][64*12];
    __shared__ uint32_t Bs[2][64*12];
    int tid = threadIdx.x;
    const __half* Ab = hu.A[z];
    const __half* Bb = hu.B[z];
    int lda = hu.lda[z], ldb = hu.ldb[z], ldc = hu.ldc[z];
    int nk = hu.K[z] >> 4;
    int m0 = blockIdx.y * 64, n0 = blockIdx.x * 64;
    int lane = tid & 31, wid = tid >> 5;
    int wmi = wid >> 2, wni = wid & 3;
    int g = lane >> 2, tg = lane & 3;
    float acc[2][2][4] = {};
    int srow = tid >> 2, sq = tid & 3;

    uint2 av = *(const uint2*)(Ab + (size_t)(m0+srow)*lda + sq*4);
    uint2 bv = *(const uint2*)(Bb + (size_t)(n0+srow)*ldb + sq*4);
    *(uint2*)&As[0][srow*12 + sq*2] = av;
    *(uint2*)&Bs[0][srow*12 + sq*2] = bv;
    __syncthreads();

    for (int kt = 0; kt < nk; kt++) {
        uint2 av2, bv2;
        if (kt + 1 < nk) {
            int k0 = (kt + 1) << 4;
            av2 = *(const uint2*)(Ab + (size_t)(m0+srow)*lda + k0 + sq*4);
            bv2 = *(const uint2*)(Bb + (size_t)(n0+srow)*ldb + k0 + sq*4);
        }
        int cur = kt & 1;
        uint32_t bf[2][2];
        #pragma unroll
        for (int nt = 0; nt < 2; nt++) {
            int nr = wni*16 + nt*8 + g;
            bf[nt][0] = Bs[cur][nr*12 + tg];
            bf[nt][1] = Bs[cur][nr*12 + 4 + tg];
        }
        #pragma unroll
        for (int mt = 0; mt < 2; mt++) {
            int rb = wmi*32 + mt*16;
            uint32_t a0 = As[cur][(rb + g    )*12 + tg];
            uint32_t a1 = As[cur][(rb + 8 + g)*12 + tg];
            uint32_t a2 = As[cur][(rb + g    )*12 + 4 + tg];
            uint32_t a3 = As[cur][(rb + 8 + g)*12 + 4 + tg];
            #pragma unroll
            for (int nt = 0; nt < 2; nt++)
                asm volatile(
                    "mma.sync.aligned.m16n8k16.row.col.f32.f16.f16.f32 "
                    "{%0,%1,%2,%3},{%4,%5,%6,%7},{%8,%9},{%0,%1,%2,%3};\n"
                    : "+f"(acc[mt][nt][0]), "+f"(acc[mt][nt][1]),
                      "+f"(acc[mt][nt][2]), "+f"(acc[mt][nt][3])
                    : "r"(a0), "r"(a1), "r"(a2), "r"(a3),
                      "r"(bf[nt][0]), "r"(bf[nt][1]));
        }
        if (kt + 1 < nk) {
            int nxt = (kt + 1) & 1;
            *(uint2*)&As[nxt][srow*12 + sq*2] = av2;
            *(uint2*)&Bs[nxt][srow*12 + sq*2] = bv2;
            __syncthreads();
        }
    }

    int mode = hu.mode[z];
    const float* bias = hu.bias[z];
    #pragma unroll
    for (int mt = 0; mt < 2; mt++) {
        int r0 = m0 + wmi*32 + mt*16 + g;
        int r1 = r0 + 8;
        float bv0 = bias ? bias[r0] : 0.0f;
        float bv1 = bias ? bias[r1] : 0.0f;
        #pragma unroll
        for (int nt = 0; nt < 2; nt++) {
            int cc = n0 + wni*16 + nt*8 + tg*2;
            float v00 = acc[mt][nt][0] + bv0, v01 = acc[mt][nt][1] + bv0;
            float v10 = acc[mt][nt][2] + bv1, v11 = acc[mt][nt][3] + bv1;
            if (mode == 0) {
                float* C = (float*)hu.C[z];
                *(float2*)&C[(size_t)r0*ldc + cc] = make_float2(v00, v01);
                *(float2*)&C[(size_t)r1*ldc + cc] = make_float2(v10, v11);
            } else if (mode == 1) {
                __half* C = (__half*)hu.C[z];
                *(__half2*)&C[(size_t)r0*ldc + cc] = __floats2half2_rn(v00, v01);
                *(__half2*)&C[(size_t)r1*ldc + cc] = __floats2half2_rn(v10, v11);
            } else {
                __half* C = (__half*)hu.C[z];
                C[(size_t)(cc  )*ldc + r0] = __float2half(v00);
                C[(size_t)(cc+1)*ldc + r0] = __float2half(v01);
                C[(size_t)(cc  )*ldc + r1] = __float2half(v10);
                C[(size_t)(cc+1)*ldc + r1] = __float2half(v11);
            }
        }
    }
}

// ---------------- softmax: warp per row of 256, fp16 in/out ----------------
__global__ void softmax_kernel()
{
    int warp = threadIdx.x >> 5, lane = threadIdx.x & 31;
    size_t row = (size_t)blockIdx.x * 8 + warp;
    const __half* rp = g_Spre + row * 256;
    uint4 u = *(const uint4*)(rp + lane * 8);
    const __half2* hp = (const __half2*)&u;
    float2 f0 = __half22float2(hp[0]);
    float2 f1 = __half22float2(hp[1]);
    float2 f2 = __half22float2(hp[2]);
    float2 f3 = __half22float2(hp[3]);
    float mx = fmaxf(fmaxf(fmaxf(f0.x, f0.y), fmaxf(f1.x, f1.y)),
                     fmaxf(fmaxf(f2.x, f2.y), fmaxf(f3.x, f3.y)));
    #pragma unroll
    for (int o = 16; o; o >>= 1) mx = fmaxf(mx, __shfl_xor_sync(0xffffffffu, mx, o));
    float e[8];
    e[0] = __expf(f0.x - mx); e[1] = __expf(f0.y - mx);
    e[2] = __expf(f1.x - mx); e[3] = __expf(f1.y - mx);
    e[4] = __expf(f2.x - mx); e[5] = __expf(f2.y - mx);
    e[6] = __expf(f3.x - mx); e[7] = __expf(f3.y - mx);
    float s = e[0]+e[1]+e[2]+e[3]+e[4]+e[5]+e[6]+e[7];
    #pragma unroll
    for (int o = 16; o; o >>= 1) s += __shfl_xor_sync(0xffffffffu, s, o);
    float inv = 1.0f / s;
    __half2 h0 = __floats2half2_rn(e[0]*inv, e[1]*inv);
    __half2 h1 = __floats2half2_rn(e[2]*inv, e[3]*inv);
    __half2 h2 = __floats2half2_rn(e[4]*inv, e[5]*inv);
    __half2 h3 = __floats2half2_rn(e[6]*inv, e[7]*inv);
    uint4 w = { *(uint32_t*)&h0, *(uint32_t*)&h1, *(uint32_t*)&h2, *(uint32_t*)&h3 };
    *(uint4*)(g_S16 + row * 256 + lane * 8) = w;
}

// ---------------- bfold ----------------
__global__ void bfold_kernel(const float* __restrict__ wm,
                             const float* __restrict__ bz,
                             const float* __restrict__ bm)
{
    int r = blockIdx.x, t = threadIdx.x;
    float s = wm[(size_t)r*768 + t] * bz[t]
            + wm[(size_t)r*768 + 256 + t] * bz[256 + t];
    __shared__ float red[8];
    #pragma unroll
    for (int o = 16; o; o >>= 1) s += __shfl_xor_sync(0xffffffffu, s, o);
    if ((t & 31) == 0) red[t >> 5] = s;
    __syncthreads();
    if (t == 0) {
        float tot = bm[r];
        #pragma unroll
        for (int i = 0; i < 8; i++) tot += red[i];
        g_bf[r] = tot;
    }
}

// ======== fused v3 (reverted): resident-A 192x256, 8 y-rows/block =========
#define FUSED_SMEM 230400
#define A_WORDS 24576
#define B_WORDS 16512
#define YG 8

__global__ void __launch_bounds__(512) fused_f16_gate(float* __restrict__ out)
{
    extern __shared__ uint32_t sm[];
    uint32_t* Asm = sm;
    int tid = threadIdx.x, lane = tid & 31, wid = tid >> 5;
    int y0 = blockIdx.x * YG;
    int m0 = blockIdx.y * 64;
    int b  = blockIdx.z;
    int wmi = wid >> 2, wni = wid & 3;
    int g = lane >> 2, tg = lane & 3;

    const __half* Xbase = g_h16 + (size_t)b * 256 * HW_;

    #pragma unroll
    for (int i = 0; i < 12; i++) {
        int slot = tid + 512*i;
        int r = slot >> 5, q32 = slot & 31;
        int grow = (r >> 6) * 256 + m0 + (r & 63);
        uint4 v = *(const uint4*)(g_w16 + (size_t)grow*256 + q32*8);
        *(uint4*)&Asm[r*128 + 4*(q32 ^ (r & 7))] = v;
    }

    int kk = tid >> 4, px8 = tid & 15;

    {
        const __half* Xy = Xbase + (size_t)y0 * 128;
        uint32_t* Bv = sm + A_WORDS;
        #pragma unroll
        for (int i = 0; i < 4; i++) {
            int kp = i*32 + kk;
            uint4 lo = *(const uint4*)(Xy + (size_t)(2*kp  )*HW_ + px8*8);
            uint4 hi = *(const uint4*)(Xy + (size_t)(2*kp+1)*HW_ + px8*8);
            const unsigned short* lp = (const unsigned short*)&lo;
            const unsigned short* hp = (const unsigned short*)&hi;
            #pragma unroll
            for (int j = 0; j < 8; j++)
                Bv[(px8*8 + j)*129 + kp] = (uint32_t)lp[j] | ((uint32_t)hp[j] << 16);
        }
    }
    __syncthreads();

    const size_t OUT2 = (size_t)B_ * 256 * HW_;

    for (int yi = 0; yi < YG; yi++) {
        int y = y0 + yi;
        uint32_t* Bcur = sm + A_WORDS + (yi & 1) * B_WORDS;

        uint4 pl[4], ph[4];
        if (yi < YG-1) {
            const __half* Xy = Xbase + (size_t)(y+1) * 128;
            #pragma unroll
            for (int i = 0; i < 4; i++) {
                int kp = i*32 + kk;
                pl[i] = *(const uint4*)(Xy + (size_t)(2*kp  )*HW_ + px8*8);
                ph[i] = *(const uint4*)(Xy + (size_t)(2*kp+1)*HW_ + px8*8);
            }
        }

        float acc[3][4][4];
        #pragma unroll
        for (int s = 0; s < 3; s++)
            #pragma unroll
            for (int n = 0; n < 4; n++)
                #pragma unroll
                for (int c = 0; c < 4; c++) acc[s][n][c] = 0.0f;

        for (int kc = 0; kc < 8; kc++) {
            #pragma unroll
            for (int ks = 0; ks < 2; ks++) {
                int kp0 = kc*16 + ks*8 + tg;
                uint32_t bfr[4][2];
                #pragma unroll
                for (int nt = 0; nt < 4; nt++) {
                    int n = wni*32 + nt*8 + g;
                    bfr[nt][0] = Bcur[n*129 + kp0];
                    bfr[nt][1] = Bcur[n*129 + kp0 + 4];
                }
                int sw0 = kp0 ^ (g << 2);
                int sw4 = sw0 ^ 4;
                #pragma unroll
                for (int s = 0; s < 3; s++) {
                    int rb = s*64 + wmi*16;
                    uint32_t a0 = Asm[(rb + g    )*128 + sw0];
                    uint32_t a1 = Asm[(rb + 8 + g)*128 + sw0];
                    uint32_t a2 = Asm[(rb + g    )*128 + sw4];
                    uint32_t a3 = Asm[(rb + 8 + g)*128 + sw4];
                    #pragma unroll
                    for (int nt = 0; nt < 4; nt++)
                        asm volatile(
                            "mma.sync.aligned.m16n8k16.row.col.f32.f16.f16.f32 "
                            "{%0,%1,%2,%3},{%4,%5,%6,%7},{%8,%9},{%0,%1,%2,%3};\n"
                            : "+f"(acc[s][nt][0]), "+f"(acc[s][nt][1]),
                              "+f"(acc[s][nt][2]), "+f"(acc[s][nt][3])
                            : "r"(a0), "r"(a1), "r"(a2), "r"(a3),
                              "r"(bfr[nt][0]), "r"(bfr[nt][1]));
                }
            }
        }
        __syncthreads();

        if (yi < YG-1) {
            uint32_t* Bnx = sm + A_WORDS + ((yi+1) & 1) * B_WORDS;
            #pragma unroll
            for (int i = 0; i < 4; i++) {
                int kp = i*32 + kk;
                const unsigned short* lp = (const unsigned short*)&pl[i];
                const unsigned short* hp = (const unsigned short*)&ph[i];
                #pragma unroll
                for (int j = 0; j < 8; j++)
                    Bnx[(px8*8 + j)*129 + kp] = (uint32_t)lp[j] | ((uint32_t)hp[j] << 16);
            }
        }

        float* gy = (float*)Bcur;
        {
            float sy = (y + 0.5f) * 0.125f - 0.5f; if (sy < 0.0f) sy = 0.0f;
            int yy0 = (int)sy; float fy = sy - (float)yy0; int yy1 = min(yy0 + 1, 15);
            #pragma unroll
            for (int i = 0; i < 6; i++) {
                int idx = tid + 512*i;
                int r = idx >> 4, px16 = idx & 15;
                int grow = (r >> 6) * 256 + m0 + (r & 63);
                const float* Gb = g_G + ((size_t)b*768 + grow) * 256;
                gy[r*16 + px16] = (1.0f - fy) * Gb[yy0*16 + px16] + fy * Gb[yy1*16 + px16];
            }
        }
        __syncthreads();

        #pragma unroll
        for (int rr = 0; rr < 2; rr++) {
            int o_loc  = wmi*16 + g + rr*8;
            int o_glob = m0 + o_loc;
            float bv0 = g_bf[o_glob];
            float bv1 = g_bf[256 + o_glob];
            float bv2 = g_bf[512 + o_glob];
            const __half* mrow = g_m16 + ((size_t)b*256 + o_glob)*HW_ + (size_t)y*128;
            float* hrow = out + ((size_t)b*256 + o_glob)*HW_ + (size_t)y*128;
            float* mrow_out = hrow + OUT2;
            #pragma unroll
            for (int nt = 0; nt < 4; nt++) {
                int x = wni*32 + nt*8 + tg*2;
                __half2 mh = *(const __half2*)&mrow[x];
                float2 mv = __half22float2(mh);
                float nh[2], nm[2];
                #pragma unroll
                for (int px = 0; px < 2; px++) {
                    int xx = x + px;
                    float sx = (xx + 0.5f) * 0.125f - 0.5f; if (sx < 0.0f) sx = 0.0f;
                    int x0 = (int)sx; float fx = sx - (float)x0; int x1 = min(x0 + 1, 15);
                    float g0 = (1.0f-fx)*gy[(0*64+o_loc)*16 + x0] + fx*gy[(0*64+o_loc)*16 + x1];
                    float g1 = (1.0f-fx)*gy[(1*64+o_loc)*16 + x0] + fx*gy[(1*64+o_loc)*16 + x1];
                    float g2 = (1.0f-fx)*gy[(2*64+o_loc)*16 + x0] + fx*gy[(2*64+o_loc)*16 + x1];
                    int cc = rr*2 + px;
                    float mo = acc[0][nt][cc] + bv0 + g0;
                    float mg = acc[1][nt][cc] + bv1 + g1;
                    float mi = acc[2][nt][cc] + bv2 + g2;
                    float mval = px ? mv.y : mv.x;
                    float gi = fast_sig(mi);
                    float nmv = (1.0f - gi) * mval + gi * fast_tanh(mg);
                    nm[px] = nmv;
                    nh[px] = nmv * fast_sig(mo);
                }
                *(float2*)&hrow[x]     = make_float2(nh[0], nh[1]);
                *(float2*)&mrow_out[x] = make_float2(nm[0], nm[1]);
            }
        }
    }
}

// ---------------- launcher ----------------
extern "C" void kernel_launch(void* const* d_in, const int* in_sizes, int n_in,
                              void* d_out, int out_size)
{
    const float* h   = (const float*)d_in[0];
    const float* m   = (const float*)d_in[1];
    const float* wq  = (const float*)d_in[2];
    const float* bq  = (const float*)d_in[3];
    const float* wk  = (const float*)d_in[4];
    const float* bk  = (const float*)d_in[5];
    const float* wv  = (const float*)d_in[6];
    const float* bv  = (const float*)d_in[7];
    const float* wkm = (const float*)d_in[8];
    const float* bkm = (const float*)d_in[9];
    const float* wvm = (const float*)d_in[10];
    const float* bvm = (const float*)d_in[11];
    const float* wz  = (const float*)d_in[12];
    const float* bz  = (const float*)d_in[13];
    const float* wm  = (const float*)d_in[14];
    const float* bm  = (const float*)d_in[15];
    float* out = (float*)d_out;

    float *G;
    __half *HpT, *MpT, *W516, *QT, *KT, *KmT, *V, *Vm, *S16, *Spre, *ZTT, *Wzz16, *wzT16, *wma16;
    cudaGetSymbolAddress((void**)&Spre,  g_Spre);
    cudaGetSymbolAddress((void**)&S16,   g_S16);
    cudaGetSymbolAddress((void**)&ZTT,   g_ZTT);
    cudaGetSymbolAddress((void**)&G,     g_G);
    cudaGetSymbolAddress((void**)&Wzz16, g_Wzz16);
    cudaGetSymbolAddress((void**)&wzT16, g_wzT16);
    cudaGetSymbolAddress((void**)&wma16, g_wma16);
    cudaGetSymbolAddress((void**)&HpT,   g_HpT);
    cudaGetSymbolAddress((void**)&MpT,   g_MpT);
    cudaGetSymbolAddress((void**)&W516,  g_W516);
    cudaGetSymbolAddress((void**)&QT,    g_QT);
    cudaGetSymbolAddress((void**)&KT,    g_KT);
    cudaGetSymbolAddress((void**)&KmT,   g_KmT);
    cudaGetSymbolAddress((void**)&V,     g_V);
    cudaGetSymbolAddress((void**)&Vm,    g_Vm);

    cudaFuncSetAttribute(fused_f16_gate,
                         cudaFuncAttributeMaxDynamicSharedMemorySize, FUSED_SMEM);

    // 1) pooling + prep + bias fold
    pool_kernel<<<dim3(8192, 2), 256>>>(h, m);
    prep_all<<<1152, 1024>>>(wm, wq, wk, wv, wkm, wvm, wz);
    bfold_kernel<<<768, 256>>>(wm, bz, bm);

    // 2) merged: Wzz fold (z=0) + all 5 projections (z=1..40)
    {
        HU hu = {};
        hu.A[0] = wma16; hu.B[0] = wzT16; hu.C[0] = Wzz16; hu.bias[0] = nullptr;
        hu.lda[0] = 512; hu.ldb[0] = 512; hu.ldc[0] = 512; hu.K[0] = 512;
        hu.mode[0] = 1; hu.mb[0] = 12; hu.nb[0] = 8;
        const __half* W5[5] = { W516 + 0*65536, W516 + 1*65536, W516 + 3*65536,
                                W516 + 2*65536, W516 + 4*65536 };
        const float*  b5[5] = { bq, bk, bkm, bv, bvm };
        __half* C5[5] = { QT, KT, KmT, V, Vm };
        const __half* in5[5] = { HpT, HpT, MpT, HpT, MpT };
        for (int s = 0; s < 5; s++)
            for (int bt = 0; bt < 8; bt++) {
                int z = 1 + s*8 + bt;
                hu.A[z] = W5[s];
                hu.B[z] = in5[s] + bt*PB;
                hu.C[z] = C5[s] + bt*PB;
                hu.bias[z] = b5[s];
                hu.lda[z] = 256; hu.ldb[z] = 256; hu.ldc[z] = 256; hu.K[z] = 256;
                hu.mode[z] = (s < 3) ? 2 : 1;
                hu.mb[z] = 4; hu.nb[z] = 4;
            }
        gemm_hu<<<dim3(8, 12, 41), 256>>>(hu);
    }

    // 3) scores (fp16 out)
    {
        HU hu = {};
        for (int z = 0; z < 16; z++) {
            int bt = z & 7;
            hu.A[z] = QT + bt*PB;
            hu.B[z] = ((z < 8) ? KT : KmT) + bt*PB;
            hu.C[z] = Spre + (long long)z*PB;
            hu.bias[z] = nullptr;
            hu.lda[z] = 256; hu.ldb[z] = 256; hu.ldc[z] = 256; hu.K[z] = 256;
            hu.mode[z] = 1; hu.mb[z] = 4; hu.nb[z] = 4;
        }
        gemm_hu<<<dim3(4, 4, 16), 256>>>(hu);
    }

    // 4) softmax -> S16
    softmax_kernel<<<512, 256>>>();

    // 5) ZTT (transposed fp16 out, ldc=512)
    {
        HU hu = {};
        for (int z = 0; z < 16; z++) {
            int bt = z & 7;
            hu.A[z] = ((z < 8) ? V : Vm) + bt*PB;
            hu.B[z] = S16 + (long long)z*PB;
            hu.C[z] = ZTT + (long long)bt*256*512 + ((z < 8) ? 0 : 256);
            hu.bias[z] = nullptr;
            hu.lda[z] = 256; hu.ldb[z] = 256; hu.ldc[z] = 512; hu.K[z] = 256;
            hu.mode[z] = 2; hu.mb[z] = 4; hu.nb[z] = 4;
        }
        gemm_hu<<<dim3(4, 4, 16), 256>>>(hu);
    }

    // 6) G = Wzz16 . ZTT  (fp32 out, K=512)
    {
        HU hu = {};
        for (int bt = 0; bt < 8; bt++) {
            hu.A[bt] = Wzz16;
            hu.B[bt] = ZTT + (long long)bt*256*512;
            hu.C[bt] = G + (long long)bt*768*256;
            hu.bias[bt] = nullptr;
            hu.lda[bt] = 512; hu.ldb[bt] = 512; hu.ldc[bt] = 256; hu.K[bt] = 512;
            hu.mode[bt] = 0; hu.mb[bt] = 12; hu.nb[bt] = 4;
        }
        gemm_hu<<<dim3(4, 12, 8), 256>>>(hu);
    }

    // 7) fused v3 (8 y-rows per block)
    fused_f16_gate<<<dim3(128/YG, 4, 8), 512, FUSED_SMEM>>>(out);
}